// round 11
// baseline (speedup 1.0000x reference)
#include <cuda_runtime.h>

// FraudGNN: 2-layer GCN, N=1M nodes (2 feats), E=32M edges ([2,E] int32 on-device).
// Algebra: GCNConv is linear => aggregate in INPUT space.
//   deg[i]   = indeg(i) + 1 (self loop);  dinv = rsqrt(deg)
//   u[i]     = dinv[i] * x[i]
//   agg1[d]  = dinv[d] * (sum_{s->d} u[s] + u[d])
//   h[i]     = relu(agg1[i] @ W1 + b1);  t[i] = h[i] @ W2;  v[i] = dinv[i]*t[i]
//   out[d]   = sigmoid( dinv[d] * (sum_{s->d} v[s] + v[d]) + b2 )
//
// 6 kernels chained with Programmatic Dependent Launch; downstream preambles
// (index/x/weight loads) overlap upstream tail drain. g_deg zero at load,
// re-zeroed by k_node1 (replay invariant). LTS sector floor ~5 ops/edge:
// deg RED + gather/RED per layer. 8 edges/thread (16 in deg), __ldcs index
// streams, float2 vector REDs in layer 1.

#define NMAX 1000000

__device__ float  g_deg [NMAX];          // zero at load; re-zeroed by k_node1
__device__ float  g_dinv[NMAX];
__device__ float2 g_u   [NMAX];
__device__ float2 g_agg [NMAX];
__device__ float  g_v   [NMAX];
__device__ int    g_is_i32;              // published by k_deg (idempotent)

// ---------------------------------------------------------------- degree (dst only) + detect
__global__ void __launch_bounds__(512)
k_deg(const void* __restrict__ ei, long long E, int n) {
    cudaTriggerProgrammaticLaunchCompletion();
    // dtype detect: int64 indices < 2^31 have zero odd 32-bit words.
    __shared__ int s_flag;
    {
        const unsigned* w = (const unsigned*)ei;
        unsigned long long nwords = 2ull * (unsigned long long)E;
        unsigned long long p = 2ull * threadIdx.x + 1ull;
        int det = (p < nwords) ? (w[p] != 0u) : 0;
        int any = __syncthreads_or(det);
        if (threadIdx.x == 0) s_flag = any;
        __syncthreads();
    }
    int is32 = s_flag;
    if (blockIdx.x == 0 && threadIdx.x == 0) g_is_i32 = is32;
    long long q = (long long)blockIdx.x * blockDim.x + threadIdx.x;
    long long e0 = 16 * q;
    if (e0 >= E) return;
    if (is32 && e0 + 16 <= E) {
        const int* p = (const int*)ei + E;                     // dst
        int4 v0 = __ldcs((const int4*)(p + e0));
        int4 v1 = __ldcs((const int4*)(p + e0) + 1);
        int4 v2 = __ldcs((const int4*)(p + e0) + 2);
        int4 v3 = __ldcs((const int4*)(p + e0) + 3);
        int d[16] = {v0.x, v0.y, v0.z, v0.w, v1.x, v1.y, v1.z, v1.w,
                     v2.x, v2.y, v2.z, v2.w, v3.x, v3.y, v3.z, v3.w};
#pragma unroll
        for (int k = 0; k < 16; k++)
            if ((unsigned)d[k] < (unsigned)n) atomicAdd(&g_deg[d[k]], 1.0f);
    } else {
        for (long long e = e0; e < e0 + 16 && e < E; e++) {
            int d = is32 ? ((const int*)ei)[E + e] : (int)((const long long*)ei)[E + e];
            if ((unsigned)d < (unsigned)n) atomicAdd(&g_deg[d], 1.0f);
        }
    }
}

// ---------------------------------------------------------------- node pass 1 (+deg reset)
__global__ void k_node1(const float* __restrict__ x, int n) {
    cudaTriggerProgrammaticLaunchCompletion();
    int i = blockIdx.x * blockDim.x + threadIdx.x;
    int i0 = 2 * i;
    if (i0 >= n) { cudaGridDependencySynchronize(); return; }
    if (i0 + 1 < n) {
        float4 xv = ((const float4*)x)[i];     // independent preamble load
        cudaGridDependencySynchronize();       // wait for k_deg's REDs
        float2 dg = ((const float2*)g_deg)[i];
        ((float2*)g_deg)[i] = make_float2(0.f, 0.f);   // restore replay invariant
        float di0 = rsqrtf(dg.x + 1.0f);
        float di1 = rsqrtf(dg.y + 1.0f);
        ((float2*)g_dinv)[i] = make_float2(di0, di1);
        float4 u = make_float4(xv.x * di0, xv.y * di0, xv.z * di1, xv.w * di1);
        ((float4*)g_u)[i]   = u;
        ((float4*)g_agg)[i] = u;               // self-loop contribution
    } else {
        float2 xv = ((const float2*)x)[i0];
        cudaGridDependencySynchronize();
        float dg = g_deg[i0];
        g_deg[i0] = 0.0f;
        float dinv = rsqrtf(dg + 1.0f);
        g_dinv[i0] = dinv;
        float2 u = make_float2(xv.x * dinv, xv.y * dinv);
        g_u[i0] = u; g_agg[i0] = u;
    }
}

// ---------------------------------------------------------------- edge pass 1: agg += u[src]
__global__ void __launch_bounds__(512)
k_edge1(const void* __restrict__ ei, long long E, int n) {
    cudaTriggerProgrammaticLaunchCompletion();
    long long q = (long long)blockIdx.x * blockDim.x + threadIdx.x;
    long long e0 = 8 * q;
    if (e0 >= E) { cudaGridDependencySynchronize(); return; }
    if (e0 + 8 <= E) {
        // optimistic i32 preamble loads (byte-safe under either dtype)
        const int* ps = (const int*)ei;
        const int* pd = (const int*)ei + E;
        int4 s0 = __ldcs((const int4*)(ps + e0));
        int4 d0 = __ldcs((const int4*)(pd + e0));
        int4 s1 = __ldcs((const int4*)(ps + e0) + 1);
        int4 d1 = __ldcs((const int4*)(pd + e0) + 1);
        cudaGridDependencySynchronize();       // wait for k_node1 (g_u, g_agg)
        if (g_is_i32) {
            int s[8] = {s0.x, s0.y, s0.z, s0.w, s1.x, s1.y, s1.z, s1.w};
            int d[8] = {d0.x, d0.y, d0.z, d0.w, d1.x, d1.y, d1.z, d1.w};
            float2 u[8];
#pragma unroll
            for (int k = 0; k < 8; k++)
                u[k] = ((unsigned)s[k] < (unsigned)n) ? __ldg(&g_u[s[k]]) : make_float2(0.f, 0.f);
#pragma unroll
            for (int k = 0; k < 8; k++)
                if ((unsigned)s[k] < (unsigned)n && (unsigned)d[k] < (unsigned)n)
                    atomicAdd(&g_agg[d[k]], u[k]);   // 64-bit vector RED
            return;
        }
    } else {
        cudaGridDependencySynchronize();
    }
    // slow path (i64 or ragged tail)
    int is32 = g_is_i32;
    for (long long e = e0; e < e0 + 8 && e < E; e++) {
        int s = is32 ? ((const int*)ei)[e]     : (int)((const long long*)ei)[e];
        int d = is32 ? ((const int*)ei)[E + e] : (int)((const long long*)ei)[E + e];
        if ((unsigned)s < (unsigned)n && (unsigned)d < (unsigned)n)
            atomicAdd(&g_agg[d], __ldg(&g_u[s]));
    }
}

// ---------------------------------------------------------------- node pass 2: MLP + init out
__global__ void k_node2(const float* __restrict__ W1, const float* __restrict__ b1,
                        const float* __restrict__ W2,
                        float* __restrict__ out, int n) {
    cudaTriggerProgrammaticLaunchCompletion();
    float w1a[8], w1b[8], bb1[8], w2[8];       // independent preamble: weights
#pragma unroll
    for (int j = 0; j < 8; j++) {
        w1a[j] = __ldg(&W1[j]); w1b[j] = __ldg(&W1[8 + j]);
        bb1[j] = __ldg(&b1[j]); w2[j]  = __ldg(&W2[j]);
    }
    cudaGridDependencySynchronize();           // wait for k_edge1 (g_agg)
    int i = blockIdx.x * blockDim.x + threadIdx.x;
    int i0 = 2 * i;
    if (i0 >= n) return;
    int lim = (i0 + 1 < n) ? 2 : 1;
    float vv[2];
#pragma unroll
    for (int m = 0; m < 2; m++) {
        if (m >= lim) break;
        int idx = i0 + m;
        float dinv = g_dinv[idx];
        float2 a   = g_agg[idx];
        float ax = a.x * dinv, ay = a.y * dinv;
        float t = 0.0f;
#pragma unroll
        for (int j = 0; j < 8; j++) {
            float y = fmaf(ax, w1a[j], fmaf(ay, w1b[j], bb1[j]));
            y = fmaxf(y, 0.0f);
            t = fmaf(y, w2[j], t);
        }
        vv[m] = t * dinv;
    }
    if (lim == 2) {
        ((float2*)g_v)[i] = make_float2(vv[0], vv[1]);
        ((float2*)out)[i] = make_float2(vv[0], vv[1]);  // self-loop init
    } else {
        g_v[i0] = vv[0];
        out[i0] = vv[0];
    }
}

// ---------------------------------------------------------------- edge pass 2: out += v[src]
__global__ void __launch_bounds__(512)
k_edge2(const void* __restrict__ ei, float* __restrict__ out,
        long long E, int n) {
    cudaTriggerProgrammaticLaunchCompletion();
    long long q = (long long)blockIdx.x * blockDim.x + threadIdx.x;
    long long e0 = 8 * q;
    if (e0 >= E) { cudaGridDependencySynchronize(); return; }
    if (e0 + 8 <= E) {
        const int* ps = (const int*)ei;
        const int* pd = (const int*)ei + E;
        int4 s0 = __ldcs((const int4*)(ps + e0));
        int4 d0 = __ldcs((const int4*)(pd + e0));
        int4 s1 = __ldcs((const int4*)(ps + e0) + 1);
        int4 d1 = __ldcs((const int4*)(pd + e0) + 1);
        cudaGridDependencySynchronize();       // wait for k_node2 (g_v, out init)
        if (g_is_i32) {
            int s[8] = {s0.x, s0.y, s0.z, s0.w, s1.x, s1.y, s1.z, s1.w};
            int d[8] = {d0.x, d0.y, d0.z, d0.w, d1.x, d1.y, d1.z, d1.w};
            float v[8];
#pragma unroll
            for (int k = 0; k < 8; k++)
                v[k] = ((unsigned)s[k] < (unsigned)n) ? __ldg(&g_v[s[k]]) : 0.0f;
#pragma unroll
            for (int k = 0; k < 8; k++)
                if ((unsigned)s[k] < (unsigned)n && (unsigned)d[k] < (unsigned)n)
                    atomicAdd(&out[d[k]], v[k]);
            return;
        }
    } else {
        cudaGridDependencySynchronize();
    }
    int is32 = g_is_i32;
    for (long long e = e0; e < e0 + 8 && e < E; e++) {
        int s = is32 ? ((const int*)ei)[e]     : (int)((const long long*)ei)[e];
        int d = is32 ? ((const int*)ei)[E + e] : (int)((const long long*)ei)[E + e];
        if ((unsigned)s < (unsigned)n && (unsigned)d < (unsigned)n)
            atomicAdd(&out[d], __ldg(&g_v[s]));
    }
}

// ---------------------------------------------------------------- final: scale + sigmoid
__global__ void k_final(float* __restrict__ out, const float* __restrict__ b2, int n) {
    float bb = __ldg(b2);                      // independent preamble
    cudaGridDependencySynchronize();           // wait for k_edge2 (out REDs)
    int i = blockIdx.x * blockDim.x + threadIdx.x;
    int i0 = 2 * i;
    if (i0 >= n) return;
    if (i0 + 1 < n) {
        float2 o  = ((const float2*)out)[i];
        float2 di = ((const float2*)g_dinv)[i];
        float z0 = fmaf(di.x, o.x, bb);
        float z1 = fmaf(di.y, o.y, bb);
        ((float2*)out)[i] = make_float2(1.0f / (1.0f + __expf(-z0)),
                                        1.0f / (1.0f + __expf(-z1)));
    } else {
        float z = fmaf(g_dinv[i0], out[i0], bb);
        out[i0] = 1.0f / (1.0f + __expf(-z));
    }
}

// ---------------------------------------------------------------- launch (PDL chain)
extern "C" void kernel_launch(void* const* d_in, const int* in_sizes, int n_in,
                              void* d_out, int out_size) {
    const float* x  = (const float*)d_in[0];
    const void*  ei = d_in[1];
    const float* W1 = (const float*)d_in[2];
    const float* b1 = (const float*)d_in[3];
    const float* W2 = (const float*)d_in[4];
    const float* b2 = (const float*)d_in[5];
    float* out = (float*)d_out;

    int       n = in_sizes[0] / 2;            // x is [N, 2]
    long long E = (long long)in_sizes[1] / 2; // edge_index is [2, E]

    const int TN = 256;                       // node kernels
    const int TE = 512;                       // edge kernels
    unsigned nb_half  = (unsigned)(((n + 1) / 2 + TN - 1) / TN);
    unsigned nb_edge8 = (unsigned)(((E + 7) / 8 + TE - 1) / TE);
    unsigned nb_deg16 = (unsigned)(((E + 15) / 16 + TE - 1) / TE);

    cudaLaunchAttribute attr[1];
    attr[0].id = cudaLaunchAttributeProgrammaticStreamSerialization;
    attr[0].val.programmaticStreamSerializationAllowed = 1;

    cudaLaunchConfig_t cfg = {};
    cfg.stream = 0;

    // first kernel: normal launch (no PSS against harness's prior stream work)
    k_deg<<<nb_deg16, TE>>>(ei, E, n);

    cfg.attrs = attr; cfg.numAttrs = 1;

    cfg.blockDim = dim3(TN, 1, 1);
    cfg.gridDim  = dim3(nb_half, 1, 1);
    cudaLaunchKernelEx(&cfg, k_node1, x, n);

    cfg.blockDim = dim3(TE, 1, 1);
    cfg.gridDim  = dim3(nb_edge8, 1, 1);
    cudaLaunchKernelEx(&cfg, k_edge1, ei, E, n);

    cfg.blockDim = dim3(TN, 1, 1);
    cfg.gridDim  = dim3(nb_half, 1, 1);
    cudaLaunchKernelEx(&cfg, k_node2, W1, b1, W2, out, n);

    cfg.blockDim = dim3(TE, 1, 1);
    cfg.gridDim  = dim3(nb_edge8, 1, 1);
    cudaLaunchKernelEx(&cfg, k_edge2, ei, out, E, n);

    cfg.blockDim = dim3(TN, 1, 1);
    cfg.gridDim  = dim3(nb_half, 1, 1);
    cudaLaunchKernelEx(&cfg, k_final, out, b2, n);
}

// round 12
// speedup vs baseline: 1.0098x; 1.0098x over previous
#include <cuda_runtime.h>

// FraudGNN: 2-layer GCN, N=1M nodes (2 feats), E=32M edges ([2,E] int32 on-device).
// Algebra: GCNConv is linear => aggregate in INPUT space.
//   deg[i]   = indeg(i) + 1 (self loop);  dinv = rsqrt(deg)
//   u[i]     = dinv[i] * x[i]
//   agg1[d]  = dinv[d] * (sum_{s->d} u[s] + u[d])
//   h[i]     = relu(agg1[i] @ W1 + b1);  t[i] = h[i] @ W2;  v[i] = dinv[i]*t[i]
//   out[d]   = sigmoid( dinv[d] * (sum_{s->d} v[s] + v[d]) + b2 )
//
// Confirmed LTS-floor config (R10): 6 kernels, PDL chain, 256T, 8 edges/thread,
// __ldcs index streams, float2 vector REDs layer 1. Edge kernels run at ~93% of
// the L2 access cap (~5.6 sector-ops/edge, algorithmically irreducible).
// This round: node kernels widened to 4 nodes/thread (float4 I/O).

#define NMAX 1000000

__device__ float  g_deg [NMAX];          // zero at load; re-zeroed by k_node1
__device__ float  g_dinv[NMAX];
__device__ float2 g_u   [NMAX];
__device__ float2 g_agg [NMAX];
__device__ float  g_v   [NMAX];
__device__ int    g_is_i32;              // published by k_deg (idempotent)

// ---------------------------------------------------------------- degree (dst only) + detect
__global__ void k_deg(const void* __restrict__ ei, long long E, int n) {
    cudaTriggerProgrammaticLaunchCompletion();
    // dtype detect: int64 indices < 2^31 have zero odd 32-bit words.
    __shared__ int s_flag;
    {
        const unsigned* w = (const unsigned*)ei;
        unsigned long long nwords = 2ull * (unsigned long long)E;
        unsigned long long p = 2ull * threadIdx.x + 1ull;
        int det = (p < nwords) ? (w[p] != 0u) : 0;
        int any = __syncthreads_or(det);
        if (threadIdx.x == 0) s_flag = any;
        __syncthreads();
    }
    int is32 = s_flag;
    if (blockIdx.x == 0 && threadIdx.x == 0) g_is_i32 = is32;
    long long q = (long long)blockIdx.x * blockDim.x + threadIdx.x;
    long long e0 = 8 * q;
    if (e0 >= E) return;
    if (is32 && e0 + 8 <= E) {
        const int* p = (const int*)ei + E;                     // dst
        int4 v0 = __ldcs((const int4*)(p + e0));
        int4 v1 = __ldcs((const int4*)(p + e0) + 1);
        int d[8] = {v0.x, v0.y, v0.z, v0.w, v1.x, v1.y, v1.z, v1.w};
#pragma unroll
        for (int k = 0; k < 8; k++)
            if ((unsigned)d[k] < (unsigned)n) atomicAdd(&g_deg[d[k]], 1.0f);
    } else {
        for (long long e = e0; e < e0 + 8 && e < E; e++) {
            int d = is32 ? ((const int*)ei)[E + e] : (int)((const long long*)ei)[E + e];
            if ((unsigned)d < (unsigned)n) atomicAdd(&g_deg[d], 1.0f);
        }
    }
}

// ---------------------------------------------------------------- node pass 1 (+deg reset), 4/thread
__global__ void k_node1(const float* __restrict__ x, int n) {
    cudaTriggerProgrammaticLaunchCompletion();
    int i = blockIdx.x * blockDim.x + threadIdx.x;
    int i0 = 4 * i;
    if (i0 >= n) { cudaGridDependencySynchronize(); return; }
    if (i0 + 3 < n) {
        float4 xv0 = ((const float4*)x)[2 * i];        // independent preamble loads
        float4 xv1 = ((const float4*)x)[2 * i + 1];
        cudaGridDependencySynchronize();               // wait for k_deg's REDs
        float4 dg = ((const float4*)g_deg)[i];
        ((float4*)g_deg)[i] = make_float4(0.f, 0.f, 0.f, 0.f);  // replay invariant
        float d0 = rsqrtf(dg.x + 1.0f);
        float d1 = rsqrtf(dg.y + 1.0f);
        float d2 = rsqrtf(dg.z + 1.0f);
        float d3 = rsqrtf(dg.w + 1.0f);
        ((float4*)g_dinv)[i] = make_float4(d0, d1, d2, d3);
        float4 u0 = make_float4(xv0.x * d0, xv0.y * d0, xv0.z * d1, xv0.w * d1);
        float4 u1 = make_float4(xv1.x * d2, xv1.y * d2, xv1.z * d3, xv1.w * d3);
        ((float4*)g_u)[2 * i]       = u0;
        ((float4*)g_u)[2 * i + 1]   = u1;
        ((float4*)g_agg)[2 * i]     = u0;              // self-loop contribution
        ((float4*)g_agg)[2 * i + 1] = u1;
    } else {
        cudaGridDependencySynchronize();
        for (int idx = i0; idx < n; idx++) {
            float dg = g_deg[idx];
            g_deg[idx] = 0.0f;
            float dinv = rsqrtf(dg + 1.0f);
            g_dinv[idx] = dinv;
            float2 xv = ((const float2*)x)[idx];
            float2 u = make_float2(xv.x * dinv, xv.y * dinv);
            g_u[idx] = u; g_agg[idx] = u;
        }
    }
}

// ---------------------------------------------------------------- edge pass 1: agg += u[src]
__global__ void k_edge1(const void* __restrict__ ei, long long E, int n) {
    cudaTriggerProgrammaticLaunchCompletion();
    long long q = (long long)blockIdx.x * blockDim.x + threadIdx.x;
    long long e0 = 8 * q;
    if (e0 >= E) { cudaGridDependencySynchronize(); return; }
    if (e0 + 8 <= E) {
        // optimistic i32 preamble loads (byte-safe under either dtype)
        const int* ps = (const int*)ei;
        const int* pd = (const int*)ei + E;
        int4 s0 = __ldcs((const int4*)(ps + e0));
        int4 d0 = __ldcs((const int4*)(pd + e0));
        int4 s1 = __ldcs((const int4*)(ps + e0) + 1);
        int4 d1 = __ldcs((const int4*)(pd + e0) + 1);
        cudaGridDependencySynchronize();       // wait for k_node1 (g_u, g_agg)
        if (g_is_i32) {
            int s[8] = {s0.x, s0.y, s0.z, s0.w, s1.x, s1.y, s1.z, s1.w};
            int d[8] = {d0.x, d0.y, d0.z, d0.w, d1.x, d1.y, d1.z, d1.w};
            float2 u[8];
#pragma unroll
            for (int k = 0; k < 8; k++)
                u[k] = ((unsigned)s[k] < (unsigned)n) ? __ldg(&g_u[s[k]]) : make_float2(0.f, 0.f);
#pragma unroll
            for (int k = 0; k < 8; k++)
                if ((unsigned)s[k] < (unsigned)n && (unsigned)d[k] < (unsigned)n)
                    atomicAdd(&g_agg[d[k]], u[k]);   // 64-bit vector RED
            return;
        }
    } else {
        cudaGridDependencySynchronize();
    }
    // slow path (i64 or ragged tail)
    int is32 = g_is_i32;
    for (long long e = e0; e < e0 + 8 && e < E; e++) {
        int s = is32 ? ((const int*)ei)[e]     : (int)((const long long*)ei)[e];
        int d = is32 ? ((const int*)ei)[E + e] : (int)((const long long*)ei)[E + e];
        if ((unsigned)s < (unsigned)n && (unsigned)d < (unsigned)n)
            atomicAdd(&g_agg[d], __ldg(&g_u[s]));
    }
}

// ---------------------------------------------------------------- node pass 2: MLP + init out
__global__ void k_node2(const float* __restrict__ W1, const float* __restrict__ b1,
                        const float* __restrict__ W2,
                        float* __restrict__ out, int n) {
    cudaTriggerProgrammaticLaunchCompletion();
    float w1a[8], w1b[8], bb1[8], w2[8];       // independent preamble: weights
#pragma unroll
    for (int j = 0; j < 8; j++) {
        w1a[j] = __ldg(&W1[j]); w1b[j] = __ldg(&W1[8 + j]);
        bb1[j] = __ldg(&b1[j]); w2[j]  = __ldg(&W2[j]);
    }
    cudaGridDependencySynchronize();           // wait for k_edge1 (g_agg)
    int i = blockIdx.x * blockDim.x + threadIdx.x;
    int i0 = 2 * i;
    if (i0 >= n) return;
    int lim = (i0 + 1 < n) ? 2 : 1;
    float vv[2];
#pragma unroll
    for (int m = 0; m < 2; m++) {
        if (m >= lim) break;
        int idx = i0 + m;
        float dinv = g_dinv[idx];
        float2 a   = g_agg[idx];
        float ax = a.x * dinv, ay = a.y * dinv;
        float t = 0.0f;
#pragma unroll
        for (int j = 0; j < 8; j++) {
            float y = fmaf(ax, w1a[j], fmaf(ay, w1b[j], bb1[j]));
            y = fmaxf(y, 0.0f);
            t = fmaf(y, w2[j], t);
        }
        vv[m] = t * dinv;
    }
    if (lim == 2) {
        ((float2*)g_v)[i] = make_float2(vv[0], vv[1]);
        ((float2*)out)[i] = make_float2(vv[0], vv[1]);  // self-loop init
    } else {
        g_v[i0] = vv[0];
        out[i0] = vv[0];
    }
}

// ---------------------------------------------------------------- edge pass 2: out += v[src]
__global__ void k_edge2(const void* __restrict__ ei, float* __restrict__ out,
                        long long E, int n) {
    cudaTriggerProgrammaticLaunchCompletion();
    long long q = (long long)blockIdx.x * blockDim.x + threadIdx.x;
    long long e0 = 8 * q;
    if (e0 >= E) { cudaGridDependencySynchronize(); return; }
    if (e0 + 8 <= E) {
        const int* ps = (const int*)ei;
        const int* pd = (const int*)ei + E;
        int4 s0 = __ldcs((const int4*)(ps + e0));
        int4 d0 = __ldcs((const int4*)(pd + e0));
        int4 s1 = __ldcs((const int4*)(ps + e0) + 1);
        int4 d1 = __ldcs((const int4*)(pd + e0) + 1);
        cudaGridDependencySynchronize();       // wait for k_node2 (g_v, out init)
        if (g_is_i32) {
            int s[8] = {s0.x, s0.y, s0.z, s0.w, s1.x, s1.y, s1.z, s1.w};
            int d[8] = {d0.x, d0.y, d0.z, d0.w, d1.x, d1.y, d1.z, d1.w};
            float v[8];
#pragma unroll
            for (int k = 0; k < 8; k++)
                v[k] = ((unsigned)s[k] < (unsigned)n) ? __ldg(&g_v[s[k]]) : 0.0f;
#pragma unroll
            for (int k = 0; k < 8; k++)
                if ((unsigned)s[k] < (unsigned)n && (unsigned)d[k] < (unsigned)n)
                    atomicAdd(&out[d[k]], v[k]);
            return;
        }
    } else {
        cudaGridDependencySynchronize();
    }
    int is32 = g_is_i32;
    for (long long e = e0; e < e0 + 8 && e < E; e++) {
        int s = is32 ? ((const int*)ei)[e]     : (int)((const long long*)ei)[e];
        int d = is32 ? ((const int*)ei)[E + e] : (int)((const long long*)ei)[E + e];
        if ((unsigned)s < (unsigned)n && (unsigned)d < (unsigned)n)
            atomicAdd(&out[d], __ldg(&g_v[s]));
    }
}

// ---------------------------------------------------------------- final: scale + sigmoid, 4/thread
__global__ void k_final(float* __restrict__ out, const float* __restrict__ b2, int n) {
    float bb = __ldg(b2);                      // independent preamble
    cudaGridDependencySynchronize();           // wait for k_edge2 (out REDs)
    int i = blockIdx.x * blockDim.x + threadIdx.x;
    int i0 = 4 * i;
    if (i0 >= n) return;
    if (i0 + 3 < n) {
        float4 o  = ((const float4*)out)[i];
        float4 di = ((const float4*)g_dinv)[i];
        float z0 = fmaf(di.x, o.x, bb);
        float z1 = fmaf(di.y, o.y, bb);
        float z2 = fmaf(di.z, o.z, bb);
        float z3 = fmaf(di.w, o.w, bb);
        ((float4*)out)[i] = make_float4(1.0f / (1.0f + __expf(-z0)),
                                        1.0f / (1.0f + __expf(-z1)),
                                        1.0f / (1.0f + __expf(-z2)),
                                        1.0f / (1.0f + __expf(-z3)));
    } else {
        for (int idx = i0; idx < n; idx++) {
            float z = fmaf(g_dinv[idx], out[idx], bb);
            out[idx] = 1.0f / (1.0f + __expf(-z));
        }
    }
}

// ---------------------------------------------------------------- launch (PDL chain)
extern "C" void kernel_launch(void* const* d_in, const int* in_sizes, int n_in,
                              void* d_out, int out_size) {
    const float* x  = (const float*)d_in[0];
    const void*  ei = d_in[1];
    const float* W1 = (const float*)d_in[2];
    const float* b1 = (const float*)d_in[3];
    const float* W2 = (const float*)d_in[4];
    const float* b2 = (const float*)d_in[5];
    float* out = (float*)d_out;

    int       n = in_sizes[0] / 2;            // x is [N, 2]
    long long E = (long long)in_sizes[1] / 2; // edge_index is [2, E]

    const int T = 256;
    unsigned nb_half = (unsigned)(((n + 1) / 2 + T - 1) / T);
    unsigned nb_quar = (unsigned)(((n + 3) / 4 + T - 1) / T);
    unsigned nb_edge = (unsigned)(((E + 7) / 8 + T - 1) / T);

    cudaLaunchAttribute attr[1];
    attr[0].id = cudaLaunchAttributeProgrammaticStreamSerialization;
    attr[0].val.programmaticStreamSerializationAllowed = 1;

    cudaLaunchConfig_t cfg = {};
    cfg.blockDim = dim3(T, 1, 1);
    cfg.stream = 0;

    // first kernel: normal launch (no PSS against harness's prior stream work)
    k_deg<<<nb_edge, T>>>(ei, E, n);

    cfg.attrs = attr; cfg.numAttrs = 1;

    cfg.gridDim = dim3(nb_quar, 1, 1);
    cudaLaunchKernelEx(&cfg, k_node1, x, n);

    cfg.gridDim = dim3(nb_edge, 1, 1);
    cudaLaunchKernelEx(&cfg, k_edge1, ei, E, n);

    cfg.gridDim = dim3(nb_half, 1, 1);
    cudaLaunchKernelEx(&cfg, k_node2, W1, b1, W2, out, n);

    cfg.gridDim = dim3(nb_edge, 1, 1);
    cudaLaunchKernelEx(&cfg, k_edge2, ei, out, E, n);

    cfg.gridDim = dim3(nb_quar, 1, 1);
    cudaLaunchKernelEx(&cfg, k_final, out, b2, n);
}

// round 13
// speedup vs baseline: 1.0128x; 1.0030x over previous
#include <cuda_runtime.h>

// FraudGNN: 2-layer GCN, N=1M nodes (2 feats), E=32M edges ([2,E] int32 on-device).
// Algebra: GCNConv is linear => aggregate in INPUT space.
//   deg[i]   = indeg(i) + 1 (self loop);  dinv = rsqrt(deg)
//   u[i]     = dinv[i] * x[i]
//   agg1[d]  = dinv[d] * (sum_{s->d} u[s] + u[d])
//   h[i]     = relu(agg1[i] @ W1 + b1);  t[i] = h[i] @ W2;  v[i] = dinv[i]*t[i]
//   out[d]   = sigmoid( dinv[d] * (sum_{s->d} v[s] + v[d]) + b2 )
//
// Converged LTS-floor config: 6 kernels, PDL chain, 256T, 8 edges/thread,
// __ldcs index streams, float2 vector REDs layer 1, node kernels 4 nodes/thread.
// Edge kernels run at ~92% of the L2 sector cap (~5.6 sector-ops/edge,
// algorithmically irreducible). g_deg zero at load; k_node1 re-zeroes (replay
// invariant).

#define NMAX 1000000

__device__ float  g_deg [NMAX];          // zero at load; re-zeroed by k_node1
__device__ float  g_dinv[NMAX];
__device__ float2 g_u   [NMAX];
__device__ float2 g_agg [NMAX];
__device__ float  g_v   [NMAX];
__device__ int    g_is_i32;              // published by k_deg (idempotent)

// ---------------------------------------------------------------- degree (dst only) + detect
__global__ void k_deg(const void* __restrict__ ei, long long E, int n) {
    cudaTriggerProgrammaticLaunchCompletion();
    // dtype detect: int64 indices < 2^31 have zero odd 32-bit words.
    __shared__ int s_flag;
    {
        const unsigned* w = (const unsigned*)ei;
        unsigned long long nwords = 2ull * (unsigned long long)E;
        unsigned long long p = 2ull * threadIdx.x + 1ull;
        int det = (p < nwords) ? (w[p] != 0u) : 0;
        int any = __syncthreads_or(det);
        if (threadIdx.x == 0) s_flag = any;
        __syncthreads();
    }
    int is32 = s_flag;
    if (blockIdx.x == 0 && threadIdx.x == 0) g_is_i32 = is32;
    long long q = (long long)blockIdx.x * blockDim.x + threadIdx.x;
    long long e0 = 8 * q;
    if (e0 >= E) return;
    if (is32 && e0 + 8 <= E) {
        const int* p = (const int*)ei + E;                     // dst
        int4 v0 = __ldcs((const int4*)(p + e0));
        int4 v1 = __ldcs((const int4*)(p + e0) + 1);
        int d[8] = {v0.x, v0.y, v0.z, v0.w, v1.x, v1.y, v1.z, v1.w};
#pragma unroll
        for (int k = 0; k < 8; k++)
            if ((unsigned)d[k] < (unsigned)n) atomicAdd(&g_deg[d[k]], 1.0f);
    } else {
        for (long long e = e0; e < e0 + 8 && e < E; e++) {
            int d = is32 ? ((const int*)ei)[E + e] : (int)((const long long*)ei)[E + e];
            if ((unsigned)d < (unsigned)n) atomicAdd(&g_deg[d], 1.0f);
        }
    }
}

// ---------------------------------------------------------------- node pass 1 (+deg reset), 4/thread
__global__ void k_node1(const float* __restrict__ x, int n) {
    cudaTriggerProgrammaticLaunchCompletion();
    int i = blockIdx.x * blockDim.x + threadIdx.x;
    int i0 = 4 * i;
    if (i0 >= n) { cudaGridDependencySynchronize(); return; }
    if (i0 + 3 < n) {
        float4 xv0 = ((const float4*)x)[2 * i];        // independent preamble loads
        float4 xv1 = ((const float4*)x)[2 * i + 1];
        cudaGridDependencySynchronize();               // wait for k_deg's REDs
        float4 dg = ((const float4*)g_deg)[i];
        ((float4*)g_deg)[i] = make_float4(0.f, 0.f, 0.f, 0.f);  // replay invariant
        float d0 = rsqrtf(dg.x + 1.0f);
        float d1 = rsqrtf(dg.y + 1.0f);
        float d2 = rsqrtf(dg.z + 1.0f);
        float d3 = rsqrtf(dg.w + 1.0f);
        ((float4*)g_dinv)[i] = make_float4(d0, d1, d2, d3);
        float4 u0 = make_float4(xv0.x * d0, xv0.y * d0, xv0.z * d1, xv0.w * d1);
        float4 u1 = make_float4(xv1.x * d2, xv1.y * d2, xv1.z * d3, xv1.w * d3);
        ((float4*)g_u)[2 * i]       = u0;
        ((float4*)g_u)[2 * i + 1]   = u1;
        ((float4*)g_agg)[2 * i]     = u0;              // self-loop contribution
        ((float4*)g_agg)[2 * i + 1] = u1;
    } else {
        cudaGridDependencySynchronize();
        for (int idx = i0; idx < n; idx++) {
            float dg = g_deg[idx];
            g_deg[idx] = 0.0f;
            float dinv = rsqrtf(dg + 1.0f);
            g_dinv[idx] = dinv;
            float2 xv = ((const float2*)x)[idx];
            float2 u = make_float2(xv.x * dinv, xv.y * dinv);
            g_u[idx] = u; g_agg[idx] = u;
        }
    }
}

// ---------------------------------------------------------------- edge pass 1: agg += u[src]
__global__ void k_edge1(const void* __restrict__ ei, long long E, int n) {
    cudaTriggerProgrammaticLaunchCompletion();
    long long q = (long long)blockIdx.x * blockDim.x + threadIdx.x;
    long long e0 = 8 * q;
    if (e0 >= E) { cudaGridDependencySynchronize(); return; }
    if (e0 + 8 <= E) {
        // optimistic i32 preamble loads (byte-safe under either dtype)
        const int* ps = (const int*)ei;
        const int* pd = (const int*)ei + E;
        int4 s0 = __ldcs((const int4*)(ps + e0));
        int4 d0 = __ldcs((const int4*)(pd + e0));
        int4 s1 = __ldcs((const int4*)(ps + e0) + 1);
        int4 d1 = __ldcs((const int4*)(pd + e0) + 1);
        cudaGridDependencySynchronize();       // wait for k_node1 (g_u, g_agg)
        if (g_is_i32) {
            int s[8] = {s0.x, s0.y, s0.z, s0.w, s1.x, s1.y, s1.z, s1.w};
            int d[8] = {d0.x, d0.y, d0.z, d0.w, d1.x, d1.y, d1.z, d1.w};
            float2 u[8];
#pragma unroll
            for (int k = 0; k < 8; k++)
                u[k] = ((unsigned)s[k] < (unsigned)n) ? __ldg(&g_u[s[k]]) : make_float2(0.f, 0.f);
#pragma unroll
            for (int k = 0; k < 8; k++)
                if ((unsigned)s[k] < (unsigned)n && (unsigned)d[k] < (unsigned)n)
                    atomicAdd(&g_agg[d[k]], u[k]);   // 64-bit vector RED
            return;
        }
    } else {
        cudaGridDependencySynchronize();
    }
    // slow path (i64 or ragged tail)
    int is32 = g_is_i32;
    for (long long e = e0; e < e0 + 8 && e < E; e++) {
        int s = is32 ? ((const int*)ei)[e]     : (int)((const long long*)ei)[e];
        int d = is32 ? ((const int*)ei)[E + e] : (int)((const long long*)ei)[E + e];
        if ((unsigned)s < (unsigned)n && (unsigned)d < (unsigned)n)
            atomicAdd(&g_agg[d], __ldg(&g_u[s]));
    }
}

// ---------------------------------------------------------------- node pass 2: MLP + init out, 4/thread
__global__ void k_node2(const float* __restrict__ W1, const float* __restrict__ b1,
                        const float* __restrict__ W2,
                        float* __restrict__ out, int n) {
    cudaTriggerProgrammaticLaunchCompletion();
    float w1a[8], w1b[8], bb1[8], w2[8];       // independent preamble: weights
#pragma unroll
    for (int j = 0; j < 8; j++) {
        w1a[j] = __ldg(&W1[j]); w1b[j] = __ldg(&W1[8 + j]);
        bb1[j] = __ldg(&b1[j]); w2[j]  = __ldg(&W2[j]);
    }
    cudaGridDependencySynchronize();           // wait for k_edge1 (g_agg)
    int i = blockIdx.x * blockDim.x + threadIdx.x;
    int i0 = 4 * i;
    if (i0 >= n) return;
    if (i0 + 3 < n) {
        float4 di = ((const float4*)g_dinv)[i];
        float4 a0 = ((const float4*)g_agg)[2 * i];      // nodes i0, i0+1
        float4 a1 = ((const float4*)g_agg)[2 * i + 1];  // nodes i0+2, i0+3
        float dv[4] = {di.x, di.y, di.z, di.w};
        float ax[4] = {a0.x * di.x, a0.z * di.y, a1.x * di.z, a1.z * di.w};
        float ay[4] = {a0.y * di.x, a0.w * di.y, a1.y * di.z, a1.w * di.w};
        float vv[4];
#pragma unroll
        for (int m = 0; m < 4; m++) {
            float t = 0.0f;
#pragma unroll
            for (int j = 0; j < 8; j++) {
                float y = fmaf(ax[m], w1a[j], fmaf(ay[m], w1b[j], bb1[j]));
                y = fmaxf(y, 0.0f);
                t = fmaf(y, w2[j], t);
            }
            vv[m] = t * dv[m];
        }
        float4 v4 = make_float4(vv[0], vv[1], vv[2], vv[3]);
        ((float4*)g_v)[i] = v4;
        ((float4*)out)[i] = v4;                // self-loop init of layer-2 accumulator
    } else {
        for (int idx = i0; idx < n; idx++) {
            float dinv = g_dinv[idx];
            float2 a   = g_agg[idx];
            float axx = a.x * dinv, ayy = a.y * dinv;
            float t = 0.0f;
#pragma unroll
            for (int j = 0; j < 8; j++) {
                float y = fmaf(axx, w1a[j], fmaf(ayy, w1b[j], bb1[j]));
                y = fmaxf(y, 0.0f);
                t = fmaf(y, w2[j], t);
            }
            float v = t * dinv;
            g_v[idx] = v;
            out[idx] = v;
        }
    }
}

// ---------------------------------------------------------------- edge pass 2: out += v[src]
__global__ void k_edge2(const void* __restrict__ ei, float* __restrict__ out,
                        long long E, int n) {
    cudaTriggerProgrammaticLaunchCompletion();
    long long q = (long long)blockIdx.x * blockDim.x + threadIdx.x;
    long long e0 = 8 * q;
    if (e0 >= E) { cudaGridDependencySynchronize(); return; }
    if (e0 + 8 <= E) {
        const int* ps = (const int*)ei;
        const int* pd = (const int*)ei + E;
        int4 s0 = __ldcs((const int4*)(ps + e0));
        int4 d0 = __ldcs((const int4*)(pd + e0));
        int4 s1 = __ldcs((const int4*)(ps + e0) + 1);
        int4 d1 = __ldcs((const int4*)(pd + e0) + 1);
        cudaGridDependencySynchronize();       // wait for k_node2 (g_v, out init)
        if (g_is_i32) {
            int s[8] = {s0.x, s0.y, s0.z, s0.w, s1.x, s1.y, s1.z, s1.w};
            int d[8] = {d0.x, d0.y, d0.z, d0.w, d1.x, d1.y, d1.z, d1.w};
            float v[8];
#pragma unroll
            for (int k = 0; k < 8; k++)
                v[k] = ((unsigned)s[k] < (unsigned)n) ? __ldg(&g_v[s[k]]) : 0.0f;
#pragma unroll
            for (int k = 0; k < 8; k++)
                if ((unsigned)s[k] < (unsigned)n && (unsigned)d[k] < (unsigned)n)
                    atomicAdd(&out[d[k]], v[k]);
            return;
        }
    } else {
        cudaGridDependencySynchronize();
    }
    int is32 = g_is_i32;
    for (long long e = e0; e < e0 + 8 && e < E; e++) {
        int s = is32 ? ((const int*)ei)[e]     : (int)((const long long*)ei)[e];
        int d = is32 ? ((const int*)ei)[E + e] : (int)((const long long*)ei)[E + e];
        if ((unsigned)s < (unsigned)n && (unsigned)d < (unsigned)n)
            atomicAdd(&out[d], __ldg(&g_v[s]));
    }
}

// ---------------------------------------------------------------- final: scale + sigmoid, 4/thread
__global__ void k_final(float* __restrict__ out, const float* __restrict__ b2, int n) {
    float bb = __ldg(b2);                      // independent preamble
    cudaGridDependencySynchronize();           // wait for k_edge2 (out REDs)
    int i = blockIdx.x * blockDim.x + threadIdx.x;
    int i0 = 4 * i;
    if (i0 >= n) return;
    if (i0 + 3 < n) {
        float4 o  = ((const float4*)out)[i];
        float4 di = ((const float4*)g_dinv)[i];
        float z0 = fmaf(di.x, o.x, bb);
        float z1 = fmaf(di.y, o.y, bb);
        float z2 = fmaf(di.z, o.z, bb);
        float z3 = fmaf(di.w, o.w, bb);
        ((float4*)out)[i] = make_float4(1.0f / (1.0f + __expf(-z0)),
                                        1.0f / (1.0f + __expf(-z1)),
                                        1.0f / (1.0f + __expf(-z2)),
                                        1.0f / (1.0f + __expf(-z3)));
    } else {
        for (int idx = i0; idx < n; idx++) {
            float z = fmaf(g_dinv[idx], out[idx], bb);
            out[idx] = 1.0f / (1.0f + __expf(-z));
        }
    }
}

// ---------------------------------------------------------------- launch (PDL chain)
extern "C" void kernel_launch(void* const* d_in, const int* in_sizes, int n_in,
                              void* d_out, int out_size) {
    const float* x  = (const float*)d_in[0];
    const void*  ei = d_in[1];
    const float* W1 = (const float*)d_in[2];
    const float* b1 = (const float*)d_in[3];
    const float* W2 = (const float*)d_in[4];
    const float* b2 = (const float*)d_in[5];
    float* out = (float*)d_out;

    int       n = in_sizes[0] / 2;            // x is [N, 2]
    long long E = (long long)in_sizes[1] / 2; // edge_index is [2, E]

    const int T = 256;
    unsigned nb_quar = (unsigned)(((n + 3) / 4 + T - 1) / T);
    unsigned nb_edge = (unsigned)(((E + 7) / 8 + T - 1) / T);

    cudaLaunchAttribute attr[1];
    attr[0].id = cudaLaunchAttributeProgrammaticStreamSerialization;
    attr[0].val.programmaticStreamSerializationAllowed = 1;

    cudaLaunchConfig_t cfg = {};
    cfg.blockDim = dim3(T, 1, 1);
    cfg.stream = 0;

    // first kernel: normal launch (no PSS against harness's prior stream work)
    k_deg<<<nb_edge, T>>>(ei, E, n);

    cfg.attrs = attr; cfg.numAttrs = 1;

    cfg.gridDim = dim3(nb_quar, 1, 1);
    cudaLaunchKernelEx(&cfg, k_node1, x, n);

    cfg.gridDim = dim3(nb_edge, 1, 1);
    cudaLaunchKernelEx(&cfg, k_edge1, ei, E, n);

    cfg.gridDim = dim3(nb_quar, 1, 1);
    cudaLaunchKernelEx(&cfg, k_node2, W1, b1, W2, out, n);

    cfg.gridDim = dim3(nb_edge, 1, 1);
    cudaLaunchKernelEx(&cfg, k_edge2, ei, out, E, n);

    cfg.gridDim = dim3(nb_quar, 1, 1);
    cudaLaunchKernelEx(&cfg, k_final, out, b2, n);
}

// round 14
// speedup vs baseline: 1.0187x; 1.0059x over previous
#include <cuda_runtime.h>

// FraudGNN: 2-layer GCN, N=1M nodes (2 feats), E=32M edges ([2,E] int32 on-device).
// Algebra: GCNConv is linear => aggregate in INPUT space.
//   deg[i]   = indeg(i) + 1 (self loop);  dinv = rsqrt(deg)
//   u[i]     = dinv[i] * x[i]
//   agg1[d]  = dinv[d] * (sum_{s->d} u[s] + u[d])
//   h[i]     = relu(agg1[i] @ W1 + b1);  t[i] = h[i] @ W2;  v[i] = dinv[i]*t[i]
//   out[d]   = sigmoid( dinv[d] * (sum_{s->d} v[s] + v[d]) + b2 )
//
// Converged LTS-floor config: 6 kernels, PDL chain, 256T, 8 edges/thread,
// __ldcs index streams, float2 vector REDs layer 1, node kernels 4 nodes/thread,
// branch-free clamped gathers. Edge kernels run at ~92% of the L2 sector cap
// (~5.6 sector-ops/edge, algorithmically irreducible for uniform-random indices).
// g_deg zero at load; k_node1 re-zeroes (replay invariant).

#define NMAX 1000000

__device__ float  g_deg [NMAX];          // zero at load; re-zeroed by k_node1
__device__ float  g_dinv[NMAX];
__device__ float2 g_u   [NMAX];
__device__ float2 g_agg [NMAX];
__device__ float  g_v   [NMAX];
__device__ int    g_is_i32;              // published by k_deg (idempotent)

// ---------------------------------------------------------------- degree (dst only) + detect
__global__ void k_deg(const void* __restrict__ ei, long long E, int n) {
    cudaTriggerProgrammaticLaunchCompletion();
    // dtype detect (warp 0): int64 indices < 2^31 have zero odd 32-bit words;
    // for int32, odd words are random indices (32 samples => P(all zero) ~ 0).
    __shared__ int s_flag;
    if (threadIdx.x < 32) {
        const unsigned* w = (const unsigned*)ei;
        unsigned long long nwords = 2ull * (unsigned long long)E;
        unsigned long long p = 2ull * threadIdx.x + 1ull;
        int det = (p < nwords) ? (w[p] != 0u) : 0;
        int any = __any_sync(0xFFFFFFFFu, det);
        if (threadIdx.x == 0) s_flag = any;
    }
    __syncthreads();
    int is32 = s_flag;
    if (blockIdx.x == 0 && threadIdx.x == 0) g_is_i32 = is32;
    long long q = (long long)blockIdx.x * blockDim.x + threadIdx.x;
    long long e0 = 8 * q;
    if (e0 >= E) return;
    if (is32 && e0 + 8 <= E) {
        const int* p = (const int*)ei + E;                     // dst
        int4 v0 = __ldcs((const int4*)(p + e0));
        int4 v1 = __ldcs((const int4*)(p + e0) + 1);
        int d[8] = {v0.x, v0.y, v0.z, v0.w, v1.x, v1.y, v1.z, v1.w};
#pragma unroll
        for (int k = 0; k < 8; k++)
            if ((unsigned)d[k] < (unsigned)n) atomicAdd(&g_deg[d[k]], 1.0f);
    } else {
        for (long long e = e0; e < e0 + 8 && e < E; e++) {
            int d = is32 ? ((const int*)ei)[E + e] : (int)((const long long*)ei)[E + e];
            if ((unsigned)d < (unsigned)n) atomicAdd(&g_deg[d], 1.0f);
        }
    }
}

// ---------------------------------------------------------------- node pass 1 (+deg reset), 4/thread
__global__ void k_node1(const float* __restrict__ x, int n) {
    cudaTriggerProgrammaticLaunchCompletion();
    int i = blockIdx.x * blockDim.x + threadIdx.x;
    int i0 = 4 * i;
    if (i0 >= n) { cudaGridDependencySynchronize(); return; }
    if (i0 + 3 < n) {
        float4 xv0 = ((const float4*)x)[2 * i];        // independent preamble loads
        float4 xv1 = ((const float4*)x)[2 * i + 1];
        cudaGridDependencySynchronize();               // wait for k_deg's REDs
        float4 dg = ((const float4*)g_deg)[i];
        ((float4*)g_deg)[i] = make_float4(0.f, 0.f, 0.f, 0.f);  // replay invariant
        float d0 = rsqrtf(dg.x + 1.0f);
        float d1 = rsqrtf(dg.y + 1.0f);
        float d2 = rsqrtf(dg.z + 1.0f);
        float d3 = rsqrtf(dg.w + 1.0f);
        ((float4*)g_dinv)[i] = make_float4(d0, d1, d2, d3);
        float4 u0 = make_float4(xv0.x * d0, xv0.y * d0, xv0.z * d1, xv0.w * d1);
        float4 u1 = make_float4(xv1.x * d2, xv1.y * d2, xv1.z * d3, xv1.w * d3);
        ((float4*)g_u)[2 * i]       = u0;
        ((float4*)g_u)[2 * i + 1]   = u1;
        ((float4*)g_agg)[2 * i]     = u0;              // self-loop contribution
        ((float4*)g_agg)[2 * i + 1] = u1;
    } else {
        cudaGridDependencySynchronize();
        for (int idx = i0; idx < n; idx++) {
            float dg = g_deg[idx];
            g_deg[idx] = 0.0f;
            float dinv = rsqrtf(dg + 1.0f);
            g_dinv[idx] = dinv;
            float2 xv = ((const float2*)x)[idx];
            float2 u = make_float2(xv.x * dinv, xv.y * dinv);
            g_u[idx] = u; g_agg[idx] = u;
        }
    }
}

// ---------------------------------------------------------------- edge pass 1: agg += u[src]
__global__ void k_edge1(const void* __restrict__ ei, long long E, int n) {
    cudaTriggerProgrammaticLaunchCompletion();
    long long q = (long long)blockIdx.x * blockDim.x + threadIdx.x;
    long long e0 = 8 * q;
    if (e0 >= E) { cudaGridDependencySynchronize(); return; }
    if (e0 + 8 <= E) {
        // optimistic i32 preamble loads (byte-safe under either dtype)
        const int* ps = (const int*)ei;
        const int* pd = (const int*)ei + E;
        int4 s0 = __ldcs((const int4*)(ps + e0));
        int4 d0 = __ldcs((const int4*)(pd + e0));
        int4 s1 = __ldcs((const int4*)(ps + e0) + 1);
        int4 d1 = __ldcs((const int4*)(pd + e0) + 1);
        cudaGridDependencySynchronize();       // wait for k_node1 (g_u, g_agg)
        if (g_is_i32) {
            int s[8] = {s0.x, s0.y, s0.z, s0.w, s1.x, s1.y, s1.z, s1.w};
            int d[8] = {d0.x, d0.y, d0.z, d0.w, d1.x, d1.y, d1.z, d1.w};
            float2 u[8];
#pragma unroll
            for (int k = 0; k < 8; k++) {
                int sc = min((unsigned)s[k], (unsigned)(n - 1)); // branch-free clamp
                u[k] = __ldg(&g_u[sc]);                          // unconditional gather
            }
#pragma unroll
            for (int k = 0; k < 8; k++)
                if ((unsigned)s[k] < (unsigned)n && (unsigned)d[k] < (unsigned)n)
                    atomicAdd(&g_agg[d[k]], u[k]);   // 64-bit vector RED (guarded)
            return;
        }
    } else {
        cudaGridDependencySynchronize();
    }
    // slow path (i64 or ragged tail)
    int is32 = g_is_i32;
    for (long long e = e0; e < e0 + 8 && e < E; e++) {
        int s = is32 ? ((const int*)ei)[e]     : (int)((const long long*)ei)[e];
        int d = is32 ? ((const int*)ei)[E + e] : (int)((const long long*)ei)[E + e];
        if ((unsigned)s < (unsigned)n && (unsigned)d < (unsigned)n)
            atomicAdd(&g_agg[d], __ldg(&g_u[s]));
    }
}

// ---------------------------------------------------------------- node pass 2: MLP + init out, 4/thread
__global__ void k_node2(const float* __restrict__ W1, const float* __restrict__ b1,
                        const float* __restrict__ W2,
                        float* __restrict__ out, int n) {
    cudaTriggerProgrammaticLaunchCompletion();
    float w1a[8], w1b[8], bb1[8], w2[8];       // independent preamble: weights
#pragma unroll
    for (int j = 0; j < 8; j++) {
        w1a[j] = __ldg(&W1[j]); w1b[j] = __ldg(&W1[8 + j]);
        bb1[j] = __ldg(&b1[j]); w2[j]  = __ldg(&W2[j]);
    }
    cudaGridDependencySynchronize();           // wait for k_edge1 (g_agg)
    int i = blockIdx.x * blockDim.x + threadIdx.x;
    int i0 = 4 * i;
    if (i0 >= n) return;
    if (i0 + 3 < n) {
        float4 di = ((const float4*)g_dinv)[i];
        float4 a0 = ((const float4*)g_agg)[2 * i];      // nodes i0, i0+1
        float4 a1 = ((const float4*)g_agg)[2 * i + 1];  // nodes i0+2, i0+3
        float dv[4] = {di.x, di.y, di.z, di.w};
        float ax[4] = {a0.x * di.x, a0.z * di.y, a1.x * di.z, a1.z * di.w};
        float ay[4] = {a0.y * di.x, a0.w * di.y, a1.y * di.z, a1.w * di.w};
        float vv[4];
#pragma unroll
        for (int m = 0; m < 4; m++) {
            float t = 0.0f;
#pragma unroll
            for (int j = 0; j < 8; j++) {
                float y = fmaf(ax[m], w1a[j], fmaf(ay[m], w1b[j], bb1[j]));
                y = fmaxf(y, 0.0f);
                t = fmaf(y, w2[j], t);
            }
            vv[m] = t * dv[m];
        }
        float4 v4 = make_float4(vv[0], vv[1], vv[2], vv[3]);
        ((float4*)g_v)[i] = v4;
        ((float4*)out)[i] = v4;                // self-loop init of layer-2 accumulator
    } else {
        for (int idx = i0; idx < n; idx++) {
            float dinv = g_dinv[idx];
            float2 a   = g_agg[idx];
            float axx = a.x * dinv, ayy = a.y * dinv;
            float t = 0.0f;
#pragma unroll
            for (int j = 0; j < 8; j++) {
                float y = fmaf(axx, w1a[j], fmaf(ayy, w1b[j], bb1[j]));
                y = fmaxf(y, 0.0f);
                t = fmaf(y, w2[j], t);
            }
            float v = t * dinv;
            g_v[idx] = v;
            out[idx] = v;
        }
    }
}

// ---------------------------------------------------------------- edge pass 2: out += v[src]
__global__ void k_edge2(const void* __restrict__ ei, float* __restrict__ out,
                        long long E, int n) {
    cudaTriggerProgrammaticLaunchCompletion();
    long long q = (long long)blockIdx.x * blockDim.x + threadIdx.x;
    long long e0 = 8 * q;
    if (e0 >= E) { cudaGridDependencySynchronize(); return; }
    if (e0 + 8 <= E) {
        const int* ps = (const int*)ei;
        const int* pd = (const int*)ei + E;
        int4 s0 = __ldcs((const int4*)(ps + e0));
        int4 d0 = __ldcs((const int4*)(pd + e0));
        int4 s1 = __ldcs((const int4*)(ps + e0) + 1);
        int4 d1 = __ldcs((const int4*)(pd + e0) + 1);
        cudaGridDependencySynchronize();       // wait for k_node2 (g_v, out init)
        if (g_is_i32) {
            int s[8] = {s0.x, s0.y, s0.z, s0.w, s1.x, s1.y, s1.z, s1.w};
            int d[8] = {d0.x, d0.y, d0.z, d0.w, d1.x, d1.y, d1.z, d1.w};
            float v[8];
#pragma unroll
            for (int k = 0; k < 8; k++) {
                int sc = min((unsigned)s[k], (unsigned)(n - 1)); // branch-free clamp
                v[k] = __ldg(&g_v[sc]);                          // unconditional gather
            }
#pragma unroll
            for (int k = 0; k < 8; k++)
                if ((unsigned)s[k] < (unsigned)n && (unsigned)d[k] < (unsigned)n)
                    atomicAdd(&out[d[k]], v[k]);
            return;
        }
    } else {
        cudaGridDependencySynchronize();
    }
    int is32 = g_is_i32;
    for (long long e = e0; e < e0 + 8 && e < E; e++) {
        int s = is32 ? ((const int*)ei)[e]     : (int)((const long long*)ei)[e];
        int d = is32 ? ((const int*)ei)[E + e] : (int)((const long long*)ei)[E + e];
        if ((unsigned)s < (unsigned)n && (unsigned)d < (unsigned)n)
            atomicAdd(&out[d], __ldg(&g_v[s]));
    }
}

// ---------------------------------------------------------------- final: scale + sigmoid, 4/thread
__global__ void k_final(float* __restrict__ out, const float* __restrict__ b2, int n) {
    float bb = __ldg(b2);                      // independent preamble
    cudaGridDependencySynchronize();           // wait for k_edge2 (out REDs)
    int i = blockIdx.x * blockDim.x + threadIdx.x;
    int i0 = 4 * i;
    if (i0 >= n) return;
    if (i0 + 3 < n) {
        float4 o  = ((const float4*)out)[i];
        float4 di = ((const float4*)g_dinv)[i];
        float z0 = fmaf(di.x, o.x, bb);
        float z1 = fmaf(di.y, o.y, bb);
        float z2 = fmaf(di.z, o.z, bb);
        float z3 = fmaf(di.w, o.w, bb);
        ((float4*)out)[i] = make_float4(1.0f / (1.0f + __expf(-z0)),
                                        1.0f / (1.0f + __expf(-z1)),
                                        1.0f / (1.0f + __expf(-z2)),
                                        1.0f / (1.0f + __expf(-z3)));
    } else {
        for (int idx = i0; idx < n; idx++) {
            float z = fmaf(g_dinv[idx], out[idx], bb);
            out[idx] = 1.0f / (1.0f + __expf(-z));
        }
    }
}

// ---------------------------------------------------------------- launch (PDL chain)
extern "C" void kernel_launch(void* const* d_in, const int* in_sizes, int n_in,
                              void* d_out, int out_size) {
    const float* x  = (const float*)d_in[0];
    const void*  ei = d_in[1];
    const float* W1 = (const float*)d_in[2];
    const float* b1 = (const float*)d_in[3];
    const float* W2 = (const float*)d_in[4];
    const float* b2 = (const float*)d_in[5];
    float* out = (float*)d_out;

    int       n = in_sizes[0] / 2;            // x is [N, 2]
    long long E = (long long)in_sizes[1] / 2; // edge_index is [2, E]

    const int T = 256;
    unsigned nb_quar = (unsigned)(((n + 3) / 4 + T - 1) / T);
    unsigned nb_edge = (unsigned)(((E + 7) / 8 + T - 1) / T);

    cudaLaunchAttribute attr[1];
    attr[0].id = cudaLaunchAttributeProgrammaticStreamSerialization;
    attr[0].val.programmaticStreamSerializationAllowed = 1;

    cudaLaunchConfig_t cfg = {};
    cfg.blockDim = dim3(T, 1, 1);
    cfg.stream = 0;

    // first kernel: normal launch (no PSS against harness's prior stream work)
    k_deg<<<nb_edge, T>>>(ei, E, n);

    cfg.attrs = attr; cfg.numAttrs = 1;

    cfg.gridDim = dim3(nb_quar, 1, 1);
    cudaLaunchKernelEx(&cfg, k_node1, x, n);

    cfg.gridDim = dim3(nb_edge, 1, 1);
    cudaLaunchKernelEx(&cfg, k_edge1, ei, E, n);

    cfg.gridDim = dim3(nb_quar, 1, 1);
    cudaLaunchKernelEx(&cfg, k_node2, W1, b1, W2, out, n);

    cfg.gridDim = dim3(nb_edge, 1, 1);
    cudaLaunchKernelEx(&cfg, k_edge2, ei, out, E, n);

    cfg.gridDim = dim3(nb_quar, 1, 1);
    cudaLaunchKernelEx(&cfg, k_final, out, b2, n);
}